// round 1
// baseline (speedup 1.0000x reference)
#include <cuda_runtime.h>
#include <math.h>

#define MAXN 50000
#define MAXE 800000
#define DIM  128

// ---- scratch (static __device__ arrays; no allocation allowed) ----
__device__ float g_q   [MAXN * DIM];
__device__ float g_k   [MAXN * DIM];
__device__ float g_v   [MAXN * DIM];
__device__ float g_skip[MAXN * DIM];
__device__ float g_qwe [MAXN * 2 * DIM];   // [N][h*128+d]
__device__ float g_z   [MAXN * 2 * DIM];   // [N][h*128+d]
__device__ float g_vagg[MAXN * DIM];
__device__ float g_pre [MAXN * DIM];
__device__ int   g_counts [MAXN];
__device__ int   g_cursor [MAXN];
__device__ int   g_offsets[MAXN + 1];
__device__ int   g_perm   [MAXE];

// ------------------------------------------------------------------
__global__ void zero_kernel(int* a, int* b, int n) {
    int i = blockIdx.x * blockDim.x + threadIdx.x;
    if (i < n) { a[i] = 0; b[i] = 0; }
}

__global__ void count_kernel(const int* __restrict__ dst, int* __restrict__ counts, int e) {
    int i = blockIdx.x * blockDim.x + threadIdx.x;
    if (i < e) atomicAdd(&counts[dst[i]], 1);
}

// single-block scan over n counts -> exclusive offsets, offsets[n] = total
__global__ void scan_kernel(const int* __restrict__ counts, int* __restrict__ offsets, int n) {
    __shared__ int part[1024];
    int tid = threadIdx.x;
    int ch = (n + 1023) >> 10;
    int b = tid * ch;
    int eidx = b + ch; if (eidx > n) eidx = n;
    int s = 0;
    for (int i = b; i < eidx; i++) s += counts[i];
    part[tid] = s;
    __syncthreads();
    for (int off = 1; off < 1024; off <<= 1) {
        int v = (tid >= off) ? part[tid - off] : 0;
        __syncthreads();
        part[tid] += v;
        __syncthreads();
    }
    int excl = (tid == 0) ? 0 : part[tid - 1];
    for (int i = b; i < eidx; i++) { offsets[i] = excl; excl += counts[i]; }
    if (tid == 1023) offsets[n] = part[1023];
}

__global__ void scatter_kernel(const int* __restrict__ dst, const int* __restrict__ offsets,
                               int* __restrict__ cursor, int* __restrict__ perm, int e) {
    int i = blockIdx.x * blockDim.x + threadIdx.x;
    if (i < e) {
        int d = dst[i];
        int pos = offsets[d] + atomicAdd(&cursor[d], 1);
        perm[pos] = i;
    }
}

// ------------------------------------------------------------------
// C[M,128] = A[M,128] @ W[128,128] + bias ; 128 threads, 8 rows/block
__global__ void gemm128_bias(const float* __restrict__ A, const float* __restrict__ W,
                             const float* __restrict__ bias, float* __restrict__ C, int M) {
    __shared__ float As[8][DIM];
    int j = threadIdx.x;
    int n0 = blockIdx.x * 8;
    for (int idx = j; idx < 8 * DIM; idx += DIM) {
        int u = idx >> 7, c = idx & 127;
        int row = n0 + u;
        As[u][c] = (row < M) ? A[(size_t)row * DIM + c] : 0.f;
    }
    __syncthreads();
    float acc[8] = {0.f, 0.f, 0.f, 0.f, 0.f, 0.f, 0.f, 0.f};
#pragma unroll 8
    for (int k = 0; k < DIM; k += 4) {
        float w0 = W[(k + 0) * DIM + j];
        float w1 = W[(k + 1) * DIM + j];
        float w2 = W[(k + 2) * DIM + j];
        float w3 = W[(k + 3) * DIM + j];
#pragma unroll
        for (int u = 0; u < 8; u++) {
            float4 a = *(const float4*)&As[u][k];
            acc[u] += a.x * w0 + a.y * w1 + a.z * w2 + a.w * w3;
        }
    }
    float bj = bias[j];
#pragma unroll
    for (int u = 0; u < 8; u++) {
        int row = n0 + u;
        if (row < M) C[(size_t)row * DIM + j] = acc[u] + bj;
    }
}

// qwe[n][h*128+d] = sum_c q[n][h*64+c] * We[d][h*64+c] ; 256 threads, 8 rows/block
__global__ void qwe_kernel(const float* __restrict__ q, const float* __restrict__ We,
                           float* __restrict__ qwe, int n) {
    __shared__ float qs[8][DIM];
    int t = threadIdx.x;
    int n0 = blockIdx.x * 8;
    for (int idx = t; idx < 8 * DIM; idx += 256) {
        int u = idx >> 7, c = idx & 127;
        int row = n0 + u;
        qs[u][c] = (row < n) ? q[(size_t)row * DIM + c] : 0.f;
    }
    __syncthreads();
    int h = t >> 7, d = t & 127;
    const float* wrow = &We[d * DIM + h * 64];
    float acc[8] = {0.f, 0.f, 0.f, 0.f, 0.f, 0.f, 0.f, 0.f};
#pragma unroll 4
    for (int c = 0; c < 64; c += 4) {
        float4 w = *(const float4*)&wrow[c];
#pragma unroll
        for (int u = 0; u < 8; u++) {
            float4 a = *(const float4*)&qs[u][h * 64 + c];
            acc[u] += a.x * w.x + a.y * w.y + a.z * w.z + a.w * w.w;
        }
    }
#pragma unroll
    for (int u = 0; u < 8; u++) {
        int row = n0 + u;
        if (row < n) qwe[(size_t)row * 256 + t] = acc[u];
    }
}

// warp-per-node online-softmax aggregation
__global__ void attn_kernel(const int* __restrict__ src_arr, const int* __restrict__ offsets,
                            const int* __restrict__ perm,
                            const float* __restrict__ q, const float* __restrict__ k,
                            const float* __restrict__ v, const float* __restrict__ qwe,
                            const float* __restrict__ edge_attr,
                            float* __restrict__ z, float* __restrict__ vagg, int n) {
    int warp = (blockIdx.x * blockDim.x + threadIdx.x) >> 5;
    int lane = threadIdx.x & 31;
    if (warp >= n) return;
    const int i = warp;
    const int beg = offsets[i], end = offsets[i + 1];
    const int head = lane >> 4;

    float4 q4 = *(const float4*)&q  [(size_t)i * 128 + lane * 4];
    float4 w0 = *(const float4*)&qwe[(size_t)i * 256 + lane * 4];
    float4 w1 = *(const float4*)&qwe[(size_t)i * 256 + 128 + lane * 4];

    float m0 = -1e30f, m1 = -1e30f, l0 = 0.f, l1 = 0.f;
    float4 az0 = make_float4(0.f, 0.f, 0.f, 0.f);
    float4 az1 = az0;
    float4 av  = az0;

    for (int t = beg; t < end; t++) {
        int e = perm[t];
        int s = src_arr[e];
        float4 ea = *(const float4*)&edge_attr[(size_t)e * 128 + lane * 4];
        float4 k4 = *(const float4*)&k[(size_t)s * 128 + lane * 4];
        float4 v4 = *(const float4*)&v[(size_t)s * 128 + lane * 4];

        float pqk = q4.x * k4.x + q4.y * k4.y + q4.z * k4.z + q4.w * k4.w;
        float p0  = ea.x * w0.x + ea.y * w0.y + ea.z * w0.z + ea.w * w0.w;
        float p1  = ea.x * w1.x + ea.y * w1.y + ea.z * w1.z + ea.w * w1.w;
#pragma unroll
        for (int off = 8; off; off >>= 1) pqk += __shfl_xor_sync(0xffffffffu, pqk, off);
#pragma unroll
        for (int off = 16; off; off >>= 1) {
            p0 += __shfl_xor_sync(0xffffffffu, p0, off);
            p1 += __shfl_xor_sync(0xffffffffu, p1, off);
        }
        float qko = __shfl_xor_sync(0xffffffffu, pqk, 16);
        float qk0 = head ? qko : pqk;
        float qk1 = head ? pqk : qko;
        float a0 = (qk0 + p0) * 0.125f;
        float a1 = (qk1 + p1) * 0.125f;

        float nm0 = fmaxf(m0, a0);
        float sc0 = __expf(m0 - nm0);
        float e0  = __expf(a0 - nm0);
        l0 = l0 * sc0 + e0; m0 = nm0;
        float nm1 = fmaxf(m1, a1);
        float sc1 = __expf(m1 - nm1);
        float e1  = __expf(a1 - nm1);
        l1 = l1 * sc1 + e1; m1 = nm1;

        az0.x = az0.x * sc0 + e0 * ea.x; az0.y = az0.y * sc0 + e0 * ea.y;
        az0.z = az0.z * sc0 + e0 * ea.z; az0.w = az0.w * sc0 + e0 * ea.w;
        az1.x = az1.x * sc1 + e1 * ea.x; az1.y = az1.y * sc1 + e1 * ea.y;
        az1.z = az1.z * sc1 + e1 * ea.z; az1.w = az1.w * sc1 + e1 * ea.w;
        float sch = head ? sc1 : sc0;
        float eh  = head ? e1  : e0;
        av.x = av.x * sch + eh * v4.x; av.y = av.y * sch + eh * v4.y;
        av.z = av.z * sch + eh * v4.z; av.w = av.w * sch + eh * v4.w;
    }

    float il0 = (end > beg) ? 1.f / l0 : 0.f;
    float il1 = (end > beg) ? 1.f / l1 : 0.f;
    float4 o0 = make_float4(az0.x * il0, az0.y * il0, az0.z * il0, az0.w * il0);
    float4 o1 = make_float4(az1.x * il1, az1.y * il1, az1.z * il1, az1.w * il1);
    *(float4*)&z[(size_t)i * 256 + lane * 4]       = o0;
    *(float4*)&z[(size_t)i * 256 + 128 + lane * 4] = o1;
    float ilh = head ? il1 : il0;
    float4 ov = make_float4(av.x * ilh, av.y * ilh, av.z * ilh, av.w * ilh);
    *(float4*)&vagg[(size_t)i * 128 + lane * 4] = ov;
}

// pre[n][j] = vagg[n][j] + skip[n][j] + sum_d z[n][h*128+d] * We[d][j]  (h = j/64)
__global__ void pre_kernel(const float* __restrict__ z, const float* __restrict__ We,
                           const float* __restrict__ vagg, const float* __restrict__ skip,
                           float* __restrict__ pre, int n) {
    __shared__ float zs[8][256];
    int j = threadIdx.x;   // 128
    int n0 = blockIdx.x * 8;
    for (int idx = j; idx < 8 * 256; idx += 128) {
        int u = idx >> 8, c = idx & 255;
        int row = n0 + u;
        zs[u][c] = (row < n) ? z[(size_t)row * 256 + c] : 0.f;
    }
    __syncthreads();
    int h = j >> 6;
    float acc[8] = {0.f, 0.f, 0.f, 0.f, 0.f, 0.f, 0.f, 0.f};
#pragma unroll 4
    for (int d = 0; d < 128; d += 4) {
        float w0 = We[(d + 0) * 128 + j];
        float w1 = We[(d + 1) * 128 + j];
        float w2 = We[(d + 2) * 128 + j];
        float w3 = We[(d + 3) * 128 + j];
#pragma unroll
        for (int u = 0; u < 8; u++) {
            float4 a = *(const float4*)&zs[u][h * 128 + d];
            acc[u] += a.x * w0 + a.y * w1 + a.z * w2 + a.w * w3;
        }
    }
#pragma unroll
    for (int u = 0; u < 8; u++) {
        int row = n0 + u;
        if (row < n)
            pre[(size_t)row * 128 + j] = acc[u] + vagg[(size_t)row * 128 + j]
                                                + skip[(size_t)row * 128 + j];
    }
}

// ------------------------------------------------------------------
extern "C" void kernel_launch(void* const* d_in, const int* in_sizes, int n_in,
                              void* d_out, int out_size) {
    const float* x     = (const float*)d_in[0];
    const float* eattr = (const float*)d_in[1];
    const float* Wq    = (const float*)d_in[2];
    const float* bq    = (const float*)d_in[3];
    const float* Wk    = (const float*)d_in[4];
    const float* bk    = (const float*)d_in[5];
    const float* Wv    = (const float*)d_in[6];
    const float* bv    = (const float*)d_in[7];
    const float* We    = (const float*)d_in[8];
    const float* Wskip = (const float*)d_in[9];
    const float* bskip = (const float*)d_in[10];
    const float* Wproj = (const float*)d_in[11];
    const float* bproj = (const float*)d_in[12];
    const int*   ei    = (const int*)d_in[13];

    const int n = in_sizes[0] / DIM;       // 50000
    const int e = in_sizes[1] / DIM;       // 800000
    const int* src = ei;                   // edge_index[0]
    const int* dst = ei + e;               // edge_index[1]

    float *pq, *pk, *pv, *pskip, *pqwe, *pz, *pvagg, *ppre;
    int *pcnt, *pcur, *poff, *pperm;
    cudaGetSymbolAddress((void**)&pq,    g_q);
    cudaGetSymbolAddress((void**)&pk,    g_k);
    cudaGetSymbolAddress((void**)&pv,    g_v);
    cudaGetSymbolAddress((void**)&pskip, g_skip);
    cudaGetSymbolAddress((void**)&pqwe,  g_qwe);
    cudaGetSymbolAddress((void**)&pz,    g_z);
    cudaGetSymbolAddress((void**)&pvagg, g_vagg);
    cudaGetSymbolAddress((void**)&ppre,  g_pre);
    cudaGetSymbolAddress((void**)&pcnt,  g_counts);
    cudaGetSymbolAddress((void**)&pcur,  g_cursor);
    cudaGetSymbolAddress((void**)&poff,  g_offsets);
    cudaGetSymbolAddress((void**)&pperm, g_perm);

    const int nb = (n + 7) / 8;

    // CSR build
    zero_kernel<<<(n + 255) / 256, 256>>>(pcnt, pcur, n);
    count_kernel<<<(e + 255) / 256, 256>>>(dst, pcnt, e);
    scan_kernel<<<1, 1024>>>(pcnt, poff, n);
    scatter_kernel<<<(e + 255) / 256, 256>>>(dst, poff, pcur, pperm, e);

    // node projections
    gemm128_bias<<<nb, 128>>>(x, Wq,    bq,    pq,    n);
    gemm128_bias<<<nb, 128>>>(x, Wk,    bk,    pk,    n);
    gemm128_bias<<<nb, 128>>>(x, Wv,    bv,    pv,    n);
    gemm128_bias<<<nb, 128>>>(x, Wskip, bskip, pskip, n);
    qwe_kernel<<<nb, 256>>>(pq, We, pqwe, n);

    // edge aggregation (warp per node, online softmax)
    attn_kernel<<<nb, 256>>>(src, poff, pperm, pq, pk, pv, pqwe, eattr, pz, pvagg, n);

    // epilogue: pre = vagg + z@We + skip ; out = pre@Wproj + bproj
    pre_kernel<<<nb, 128>>>(pz, We, pvagg, pskip, ppre, n);
    gemm128_bias<<<nb, 128>>>(ppre, Wproj, bproj, (float*)d_out, n);
}